// round 9
// baseline (speedup 1.0000x reference)
#include <cuda_runtime.h>
#include <math.h>

#define OUT_COLS 2883

// scratch: batch-0 features transposed to [H,W,C], concatenated per scale
//   s0: [56*56,64]  @ 0        s1: [28*28,128] @ 200704
//   s2: [14*14,256] @ 301056   s3: [7*7,512]   @ 351232
__device__ float g_scratch[376320];
// consts: [0..8] Minv[d][k], [9..11] o0; per view v at 12+v*12: c[v][k][d], o_v at +9..11
__device__ float g_consts[12 + 3 * 12];

// Fused: feature transpose (all blocks) + camera constants (block 0, threads 0-2)
__global__ void prep_kernel(const float* __restrict__ f0,
                            const float* __restrict__ f1,
                            const float* __restrict__ f2,
                            const float* __restrict__ f3,
                            const float* __restrict__ cameras) {
    if (blockIdx.x == 0 && threadIdx.x < 3) {
        const float PIF = 3.14159274101257324f;
        int v = threadIdx.x;
        float th = cameras[v * 5 + 0] * (PIF / 180.0f);
        float ph = cameras[v * 5 + 1] * (PIF / 180.0f);
        float r  = cameras[v * 5 + 3];
        float camy = r * sinf(ph);
        float lens = r * cosf(ph);
        float camx = lens * cosf(th);
        float camz = lens * sinf(th);
        float Z[3] = {camx, camy, camz};
        float Y[3] = {camy * cosf(th + PIF), lens, camy * sinf(th + PIF)};
        float X[3] = {Y[1] * Z[2] - Y[2] * Z[1],
                      Y[2] * Z[0] - Y[0] * Z[2],
                      Y[0] * Z[1] - Y[1] * Z[0]};
        float nx = sqrtf(X[0]*X[0] + X[1]*X[1] + X[2]*X[2]);
        float ny = sqrtf(Y[0]*Y[0] + Y[1]*Y[1] + Y[2]*Y[2]);
        float nz = sqrtf(Z[0]*Z[0] + Z[1]*Z[1] + Z[2]*Z[2]);
        float cn[3][3];
        for (int d = 0; d < 3; d++) {
            cn[0][d] = X[d] / nx;
            cn[1][d] = Y[d] / ny;
            cn[2][d] = Z[d] / nz;
        }
        for (int k = 0; k < 3; k++)
            for (int d = 0; d < 3; d++)
                g_consts[12 + v * 12 + k * 3 + d] = cn[k][d];
        for (int d = 0; d < 3; d++)
            g_consts[12 + v * 12 + 9 + d] = Z[d];

        if (v == 0) {
            double A[3][3];
            for (int i = 0; i < 3; i++)
                for (int j = 0; j < 3; j++)
                    A[i][j] = (double)cn[j][i];
            double det = A[0][0] * (A[1][1]*A[2][2] - A[1][2]*A[2][1])
                       + A[0][1] * (A[1][2]*A[2][0] - A[1][0]*A[2][2])
                       + A[0][2] * (A[1][0]*A[2][1] - A[1][1]*A[2][0]);
            double inv[3][3];
            inv[0][0] = (A[1][1]*A[2][2] - A[1][2]*A[2][1]) / det;
            inv[0][1] = (A[0][2]*A[2][1] - A[0][1]*A[2][2]) / det;
            inv[0][2] = (A[0][1]*A[1][2] - A[0][2]*A[1][1]) / det;
            inv[1][0] = (A[1][2]*A[2][0] - A[1][0]*A[2][2]) / det;
            inv[1][1] = (A[0][0]*A[2][2] - A[0][2]*A[2][0]) / det;
            inv[1][2] = (A[0][2]*A[1][0] - A[0][0]*A[1][2]) / det;
            inv[2][0] = (A[1][0]*A[2][1] - A[1][1]*A[2][0]) / det;
            inv[2][1] = (A[0][1]*A[2][0] - A[0][0]*A[2][1]) / det;
            inv[2][2] = (A[0][0]*A[1][1] - A[0][1]*A[1][0]) / det;
            for (int d = 0; d < 3; d++)
                for (int k = 0; k < 3; k++)
                    g_consts[d * 3 + k] = (float)inv[d][k];
            for (int d = 0; d < 3; d++)
                g_consts[9 + d] = Z[d];
        }
    }

    int i = blockIdx.x * blockDim.x + threadIdx.x;
    if (i >= 376320) return;
    float v;
    if (i < 200704)      { int c = i & 63;  int p = i >> 6;                 v = f0[c * 3136 + p]; }
    else if (i < 301056) { int l = i - 200704; int c = l & 127; int p = l >> 7; v = f1[c * 784 + p]; }
    else if (i < 351232) { int l = i - 301056; int c = l & 255; int p = l >> 8; v = f2[c * 196 + p]; }
    else                 { int l = i - 351232; int c = l & 511; int p = l >> 9; v = f3[c * 49 + p]; }
    g_scratch[i] = v;
}

// gather one channel's (a,b,d); bases come from shared (broadcast LDS, saves regs)
__device__ __forceinline__ void gather3s(int c, const int* sb,
                                         float& a, float& b, float& d) {
    int s, l;
    if (c < 64)       { s = 0; l = c; }
    else if (c < 192) { s = 1; l = c - 64; }
    else if (c < 448) { s = 2; l = c - 192; }
    else              { s = 3; l = c - 448; }
    a = __ldg(&g_scratch[sb[s] + l]);
    b = __ldg(&g_scratch[sb[4 + s] + l]);
    d = __ldg(&g_scratch[sb[8 + s] + l]);
}

__device__ __forceinline__ void stats(float a, float b, float d,
                                      float& mx, float& mn, float& sd) {
    mx = fmaxf(a, fmaxf(b, d));
    mn = (a + b + d) * (1.0f / 3.0f);
    float e0 = a - mn, e1 = b - mn, e2 = d - mn;
    sd = sqrtf((e0 * e0 + e1 * e1 + e2 * e2) * (1.0f / 3.0f));
}

__global__ __launch_bounds__(256, 8) void main_kernel(const float* __restrict__ inputs,
                                                      float* __restrict__ out) {
    __shared__ int sb[12];   // [v*4 + s]
    int row = blockIdx.x;
    int tid = threadIdx.x;
    size_t base = (size_t)row * OUT_COLS;

    if (tid < 3) {
        int v = tid;
        float in0 = inputs[row * 3 + 0];
        float in1 = inputs[row * 3 + 1];
        float in2 = inputs[row * 3 + 2];
        const float* C = g_consts;
        float po[3];
        #pragma unroll
        for (int k = 0; k < 3; k++)
            po[k] = fmaf(in0, C[0 * 3 + k],
                    fmaf(in1, C[1 * 3 + k],
                    fmaf(in2, C[2 * 3 + k], C[9 + k])));
        const float* cv = C + 12 + v * 12;
        float d0 = po[0] - cv[9];
        float d1 = po[1] - cv[10];
        float d2 = po[2] - cv[11];
        float X = fmaf(d0, cv[0], fmaf(d1, cv[1], d2 * cv[2]));
        float Y = fmaf(d0, cv[3], fmaf(d1, cv[4], d2 * cv[5]));
        float Z = fmaf(d0, cv[6], fmaf(d1, cv[7], d2 * cv[8]));
        float nz = -Z;
        float h = fmaf(248.0f, __fdiv_rn(-Y, nz), 112.0f);
        float w = fmaf(248.0f, __fdiv_rn(X, nz), 112.0f);
        if (isnan(h)) h = 0.0f;
        if (isnan(w)) w = 0.0f;
        h = fminf(fmaxf(h, 0.0f), 223.0f);
        w = fminf(fmaxf(w, 0.0f), 223.0f);
        int h0 = (int)(h * 0.25f),    w0 = (int)(w * 0.25f);
        int h1 = (int)(h * 0.125f),   w1 = (int)(w * 0.125f);
        int h2 = (int)(h * 0.0625f),  w2 = (int)(w * 0.0625f);
        int h3 = (int)(h * 0.03125f), w3 = (int)(w * 0.03125f);
        sb[v * 4 + 0] = (h0 * 56 + w0) * 64;
        sb[v * 4 + 1] = 200704 + (h1 * 28 + w1) * 128;
        sb[v * 4 + 2] = 301056 + (h2 * 14 + w2) * 256;
        sb[v * 4 + 3] = 351232 + (h3 * 7 + w3) * 512;
        __stcs(&out[base + v], (v == 0) ? in0 : (v == 1) ? in1 : in2);
    }
    __syncthreads();

    float* orow = out + base + 3;                   // channel 0 of section 0
    int d0 = (int)((4 - ((base + 3) & 3)) & 3);     // first 16B-aligned channel
    int nq = (960 - d0) >> 2;                       // full quads (240 or 239)

    if (tid < nq) {
        int c0 = d0 + 4 * tid;
        float4 mx4, mn4, sd4;
        {
            float a, b, d;
            gather3s(c0 + 0, sb, a, b, d); stats(a, b, d, mx4.x, mn4.x, sd4.x);
            gather3s(c0 + 1, sb, a, b, d); stats(a, b, d, mx4.y, mn4.y, sd4.y);
            gather3s(c0 + 2, sb, a, b, d); stats(a, b, d, mx4.z, mn4.z, sd4.z);
            gather3s(c0 + 3, sb, a, b, d); stats(a, b, d, mx4.w, mn4.w, sd4.w);
        }
        __stcs((float4*)(orow + c0), mx4);
        __stcs((float4*)(orow + 960 + c0), mn4);
        __stcs((float4*)(orow + 1920 + c0), sd4);
    } else if (d0 && tid >= 248 && tid < 252) {
        // edge channels: {0..d0-1} and {d0+4*nq .. 959}; uniformly e<d0?e:956+e
        int e = tid - 248;
        int c = (e < d0) ? e : 956 + e;
        if (c < 960) {
            float a, b, d;
            gather3s(c, sb, a, b, d);
            float mx, mn, sd;
            stats(a, b, d, mx, mn, sd);
            __stcs(&orow[c], mx);
            __stcs(&orow[960 + c], mn);
            __stcs(&orow[1920 + c], sd);
        }
    }
}

extern "C" void kernel_launch(void* const* d_in, const int* in_sizes, int n_in,
                              void* d_out, int out_size) {
    const float* inputs  = (const float*)d_in[0];
    const float* cameras = (const float*)d_in[1];
    const float* f0 = (const float*)d_in[2];
    const float* f1 = (const float*)d_in[3];
    const float* f2 = (const float*)d_in[4];
    const float* f3 = (const float*)d_in[5];
    float* out = (float*)d_out;

    int n = in_sizes[0] / 3;

    prep_kernel<<<(376320 + 255) / 256, 256>>>(f0, f1, f2, f3, cameras);
    main_kernel<<<n, 256>>>(inputs, out);
}

// round 10
// speedup vs baseline: 1.0215x; 1.0215x over previous
#include <cuda_runtime.h>
#include <math.h>

#define OUT_COLS 2883

// scratch: batch-0 features transposed to [H,W,C], concatenated per scale
//   s0: [56*56,64]  @ 0        s1: [28*28,128] @ 200704
//   s2: [14*14,256] @ 301056   s3: [7*7,512]   @ 351232
__device__ float g_scratch[376320];
// consts: [0..8] Minv[d][k], [9..11] o0; per view v at 12+v*12: c[v][k][d], o_v at +9..11
__device__ float g_consts[12 + 3 * 12];

// Fused: feature transpose (all blocks) + camera constants (block 0, threads 0-2)
__global__ void prep_kernel(const float* __restrict__ f0,
                            const float* __restrict__ f1,
                            const float* __restrict__ f2,
                            const float* __restrict__ f3,
                            const float* __restrict__ cameras) {
    if (blockIdx.x == 0 && threadIdx.x < 3) {
        const float PIF = 3.14159274101257324f;
        int v = threadIdx.x;
        float th = cameras[v * 5 + 0] * (PIF / 180.0f);
        float ph = cameras[v * 5 + 1] * (PIF / 180.0f);
        float r  = cameras[v * 5 + 3];
        float camy = r * sinf(ph);
        float lens = r * cosf(ph);
        float camx = lens * cosf(th);
        float camz = lens * sinf(th);
        float Z[3] = {camx, camy, camz};
        float Y[3] = {camy * cosf(th + PIF), lens, camy * sinf(th + PIF)};
        float X[3] = {Y[1] * Z[2] - Y[2] * Z[1],
                      Y[2] * Z[0] - Y[0] * Z[2],
                      Y[0] * Z[1] - Y[1] * Z[0]};
        float nx = sqrtf(X[0]*X[0] + X[1]*X[1] + X[2]*X[2]);
        float ny = sqrtf(Y[0]*Y[0] + Y[1]*Y[1] + Y[2]*Y[2]);
        float nz = sqrtf(Z[0]*Z[0] + Z[1]*Z[1] + Z[2]*Z[2]);
        float cn[3][3];
        for (int d = 0; d < 3; d++) {
            cn[0][d] = X[d] / nx;
            cn[1][d] = Y[d] / ny;
            cn[2][d] = Z[d] / nz;
        }
        for (int k = 0; k < 3; k++)
            for (int d = 0; d < 3; d++)
                g_consts[12 + v * 12 + k * 3 + d] = cn[k][d];
        for (int d = 0; d < 3; d++)
            g_consts[12 + v * 12 + 9 + d] = Z[d];

        if (v == 0) {
            double A[3][3];
            for (int i = 0; i < 3; i++)
                for (int j = 0; j < 3; j++)
                    A[i][j] = (double)cn[j][i];
            double det = A[0][0] * (A[1][1]*A[2][2] - A[1][2]*A[2][1])
                       + A[0][1] * (A[1][2]*A[2][0] - A[1][0]*A[2][2])
                       + A[0][2] * (A[1][0]*A[2][1] - A[1][1]*A[2][0]);
            double inv[3][3];
            inv[0][0] = (A[1][1]*A[2][2] - A[1][2]*A[2][1]) / det;
            inv[0][1] = (A[0][2]*A[2][1] - A[0][1]*A[2][2]) / det;
            inv[0][2] = (A[0][1]*A[1][2] - A[0][2]*A[1][1]) / det;
            inv[1][0] = (A[1][2]*A[2][0] - A[1][0]*A[2][2]) / det;
            inv[1][1] = (A[0][0]*A[2][2] - A[0][2]*A[2][0]) / det;
            inv[1][2] = (A[0][2]*A[1][0] - A[0][0]*A[1][2]) / det;
            inv[2][0] = (A[1][0]*A[2][1] - A[1][1]*A[2][0]) / det;
            inv[2][1] = (A[0][1]*A[2][0] - A[0][0]*A[2][1]) / det;
            inv[2][2] = (A[0][0]*A[1][1] - A[0][1]*A[1][0]) / det;
            for (int d = 0; d < 3; d++)
                for (int k = 0; k < 3; k++)
                    g_consts[d * 3 + k] = (float)inv[d][k];
            for (int d = 0; d < 3; d++)
                g_consts[9 + d] = Z[d];
        }
    }

    int i = blockIdx.x * blockDim.x + threadIdx.x;
    if (i >= 376320) return;
    float v;
    if (i < 200704)      { int c = i & 63;  int p = i >> 6;                 v = f0[c * 3136 + p]; }
    else if (i < 301056) { int l = i - 200704; int c = l & 127; int p = l >> 7; v = f1[c * 784 + p]; }
    else if (i < 351232) { int l = i - 301056; int c = l & 255; int p = l >> 8; v = f2[c * 196 + p]; }
    else                 { int l = i - 351232; int c = l & 511; int p = l >> 9; v = f3[c * 49 + p]; }
    g_scratch[i] = v;
}

// gather one channel's (a,b,d); bases come from shared (broadcast LDS, saves regs)
__device__ __forceinline__ void gather3s(int c, const int* sb,
                                         float& a, float& b, float& d) {
    int s, l;
    if (c < 64)       { s = 0; l = c; }
    else if (c < 192) { s = 1; l = c - 64; }
    else if (c < 448) { s = 2; l = c - 192; }
    else              { s = 3; l = c - 448; }
    a = __ldg(&g_scratch[sb[s] + l]);
    b = __ldg(&g_scratch[sb[4 + s] + l]);
    d = __ldg(&g_scratch[sb[8 + s] + l]);
}

__device__ __forceinline__ void stats(float a, float b, float d,
                                      float& mx, float& mn, float& sd) {
    mx = fmaxf(a, fmaxf(b, d));
    mn = (a + b + d) * (1.0f / 3.0f);
    float e0 = a - mn, e1 = b - mn, e2 = d - mn;
    sd = sqrtf((e0 * e0 + e1 * e1 + e2 * e2) * (1.0f / 3.0f));
}

__global__ __launch_bounds__(512, 4) void main_kernel(const float* __restrict__ inputs,
                                                      float* __restrict__ out) {
    __shared__ int sb[12];   // [v*4 + s]
    int row = blockIdx.x;
    int tid = threadIdx.x;
    size_t base = (size_t)row * OUT_COLS;

    if (tid < 3) {
        int v = tid;
        float in0 = inputs[row * 3 + 0];
        float in1 = inputs[row * 3 + 1];
        float in2 = inputs[row * 3 + 2];
        const float* C = g_consts;
        float po[3];
        #pragma unroll
        for (int k = 0; k < 3; k++)
            po[k] = fmaf(in0, C[0 * 3 + k],
                    fmaf(in1, C[1 * 3 + k],
                    fmaf(in2, C[2 * 3 + k], C[9 + k])));
        const float* cv = C + 12 + v * 12;
        float d0 = po[0] - cv[9];
        float d1 = po[1] - cv[10];
        float d2 = po[2] - cv[11];
        float X = fmaf(d0, cv[0], fmaf(d1, cv[1], d2 * cv[2]));
        float Y = fmaf(d0, cv[3], fmaf(d1, cv[4], d2 * cv[5]));
        float Z = fmaf(d0, cv[6], fmaf(d1, cv[7], d2 * cv[8]));
        float nz = -Z;
        float h = fmaf(248.0f, __fdiv_rn(-Y, nz), 112.0f);
        float w = fmaf(248.0f, __fdiv_rn(X, nz), 112.0f);
        if (isnan(h)) h = 0.0f;
        if (isnan(w)) w = 0.0f;
        h = fminf(fmaxf(h, 0.0f), 223.0f);
        w = fminf(fmaxf(w, 0.0f), 223.0f);
        int h0 = (int)(h * 0.25f),    w0 = (int)(w * 0.25f);
        int h1 = (int)(h * 0.125f),   w1 = (int)(w * 0.125f);
        int h2 = (int)(h * 0.0625f),  w2 = (int)(w * 0.0625f);
        int h3 = (int)(h * 0.03125f), w3 = (int)(w * 0.03125f);
        sb[v * 4 + 0] = (h0 * 56 + w0) * 64;
        sb[v * 4 + 1] = 200704 + (h1 * 28 + w1) * 128;
        sb[v * 4 + 2] = 301056 + (h2 * 14 + w2) * 256;
        sb[v * 4 + 3] = 351232 + (h3 * 7 + w3) * 512;
        __stcs(&out[base + v], (v == 0) ? in0 : (v == 1) ? in1 : in2);
    }
    __syncthreads();

    float* orow = out + base + 3;              // channel 0 of section 0
    int gamma = (int)((base + 3) & 1);         // 0 -> channel addr even at c=0
    int npairs = 480 - gamma;                  // pairs c0 = gamma + 2*tid

    if (tid < npairs) {
        int c0 = gamma + 2 * tid;
        float ax, bx, dx, ay, by, dy;
        if (tid >= 224) {
            // c0 >= 448+gamma >= 449 (and c0=448 only when gamma=0,tid=224 -> still s3)
            int l = c0 - 448;
            const int* sb3 = sb;
            ax = __ldg(&g_scratch[sb3[3] + l]);
            bx = __ldg(&g_scratch[sb3[7] + l]);
            dx = __ldg(&g_scratch[sb3[11] + l]);
            ay = __ldg(&g_scratch[sb3[3] + l + 1]);
            by = __ldg(&g_scratch[sb3[7] + l + 1]);
            dy = __ldg(&g_scratch[sb3[11] + l + 1]);
        } else {
            gather3s(c0,     sb, ax, bx, dx);
            gather3s(c0 + 1, sb, ay, by, dy);
        }
        float2 mx2, mn2, sd2;
        stats(ax, bx, dx, mx2.x, mn2.x, sd2.x);
        stats(ay, by, dy, mx2.y, mn2.y, sd2.y);
        __stcs((float2*)(orow + c0), mx2);
        __stcs((float2*)(orow + 960 + c0), mn2);
        __stcs((float2*)(orow + 1920 + c0), sd2);
    } else if (gamma && tid >= 504 && tid < 506) {
        // edge channels 0 and 959 (scalar), on otherwise-idle lanes
        int c = (tid == 504) ? 0 : 959;
        float a, b, d;
        gather3s(c, sb, a, b, d);
        float mx, mn, sd;
        stats(a, b, d, mx, mn, sd);
        __stcs(&orow[c], mx);
        __stcs(&orow[960 + c], mn);
        __stcs(&orow[1920 + c], sd);
    }
}

extern "C" void kernel_launch(void* const* d_in, const int* in_sizes, int n_in,
                              void* d_out, int out_size) {
    const float* inputs  = (const float*)d_in[0];
    const float* cameras = (const float*)d_in[1];
    const float* f0 = (const float*)d_in[2];
    const float* f1 = (const float*)d_in[3];
    const float* f2 = (const float*)d_in[4];
    const float* f3 = (const float*)d_in[5];
    float* out = (float*)d_out;

    int n = in_sizes[0] / 3;

    prep_kernel<<<(376320 + 255) / 256, 256>>>(f0, f1, f2, f3, cameras);
    main_kernel<<<n, 512>>>(inputs, out);
}

// round 11
// speedup vs baseline: 1.3235x; 1.2957x over previous
#include <cuda_runtime.h>
#include <math.h>

#define OUT_COLS 2883

// scratch: batch-0 features transposed to [H,W,C], concatenated per scale
//   s0: [56*56,64]  @ 0        s1: [28*28,128] @ 200704
//   s2: [14*14,256] @ 301056   s3: [7*7,512]   @ 351232
__device__ float g_scratch[376320];
// consts: [0..8] Minv[d][k], [9..11] o0; per view v at 12+v*12: c[v][k][d], o_v at +9..11
__device__ float g_consts[12 + 3 * 12];

// Fused: feature transpose (all blocks) + camera constants (block 0, threads 0-2)
__global__ void prep_kernel(const float* __restrict__ f0,
                            const float* __restrict__ f1,
                            const float* __restrict__ f2,
                            const float* __restrict__ f3,
                            const float* __restrict__ cameras) {
    if (blockIdx.x == 0 && threadIdx.x < 3) {
        const float PIF = 3.14159274101257324f;
        int v = threadIdx.x;
        float th = cameras[v * 5 + 0] * (PIF / 180.0f);
        float ph = cameras[v * 5 + 1] * (PIF / 180.0f);
        float r  = cameras[v * 5 + 3];
        float camy = r * sinf(ph);
        float lens = r * cosf(ph);
        float camx = lens * cosf(th);
        float camz = lens * sinf(th);
        float Z[3] = {camx, camy, camz};
        float Y[3] = {camy * cosf(th + PIF), lens, camy * sinf(th + PIF)};
        float X[3] = {Y[1] * Z[2] - Y[2] * Z[1],
                      Y[2] * Z[0] - Y[0] * Z[2],
                      Y[0] * Z[1] - Y[1] * Z[0]};
        float nx = sqrtf(X[0]*X[0] + X[1]*X[1] + X[2]*X[2]);
        float ny = sqrtf(Y[0]*Y[0] + Y[1]*Y[1] + Y[2]*Y[2]);
        float nz = sqrtf(Z[0]*Z[0] + Z[1]*Z[1] + Z[2]*Z[2]);
        float cn[3][3];
        for (int d = 0; d < 3; d++) {
            cn[0][d] = X[d] / nx;
            cn[1][d] = Y[d] / ny;
            cn[2][d] = Z[d] / nz;
        }
        for (int k = 0; k < 3; k++)
            for (int d = 0; d < 3; d++)
                g_consts[12 + v * 12 + k * 3 + d] = cn[k][d];
        for (int d = 0; d < 3; d++)
            g_consts[12 + v * 12 + 9 + d] = Z[d];

        if (v == 0) {
            double A[3][3];
            for (int i = 0; i < 3; i++)
                for (int j = 0; j < 3; j++)
                    A[i][j] = (double)cn[j][i];
            double det = A[0][0] * (A[1][1]*A[2][2] - A[1][2]*A[2][1])
                       + A[0][1] * (A[1][2]*A[2][0] - A[1][0]*A[2][2])
                       + A[0][2] * (A[1][0]*A[2][1] - A[1][1]*A[2][0]);
            double inv[3][3];
            inv[0][0] = (A[1][1]*A[2][2] - A[1][2]*A[2][1]) / det;
            inv[0][1] = (A[0][2]*A[2][1] - A[0][1]*A[2][2]) / det;
            inv[0][2] = (A[0][1]*A[1][2] - A[0][2]*A[1][1]) / det;
            inv[1][0] = (A[1][2]*A[2][0] - A[1][0]*A[2][2]) / det;
            inv[1][1] = (A[0][0]*A[2][2] - A[0][2]*A[2][0]) / det;
            inv[1][2] = (A[0][2]*A[1][0] - A[0][0]*A[1][2]) / det;
            inv[2][0] = (A[1][0]*A[2][1] - A[1][1]*A[2][0]) / det;
            inv[2][1] = (A[0][1]*A[2][0] - A[0][0]*A[2][1]) / det;
            inv[2][2] = (A[0][0]*A[1][1] - A[0][1]*A[1][0]) / det;
            for (int d = 0; d < 3; d++)
                for (int k = 0; k < 3; k++)
                    g_consts[d * 3 + k] = (float)inv[d][k];
            for (int d = 0; d < 3; d++)
                g_consts[9 + d] = Z[d];
        }
    }

    int i = blockIdx.x * blockDim.x + threadIdx.x;
    if (i >= 376320) return;
    float v;
    if (i < 200704)      { int c = i & 63;  int p = i >> 6;                 v = f0[c * 3136 + p]; }
    else if (i < 301056) { int l = i - 200704; int c = l & 127; int p = l >> 7; v = f1[c * 784 + p]; }
    else if (i < 351232) { int l = i - 301056; int c = l & 255; int p = l >> 8; v = f2[c * 196 + p]; }
    else                 { int l = i - 351232; int c = l & 511; int p = l >> 9; v = f3[c * 49 + p]; }
    g_scratch[i] = v;
}

// gather one channel's (a,b,d); bases come from shared (broadcast LDS, saves regs)
__device__ __forceinline__ void gather3s(int c, const int* sb,
                                         float& a, float& b, float& d) {
    int s, l;
    if (c < 64)       { s = 0; l = c; }
    else if (c < 192) { s = 1; l = c - 64; }
    else if (c < 448) { s = 2; l = c - 192; }
    else              { s = 3; l = c - 448; }
    a = __ldg(&g_scratch[sb[s] + l]);
    b = __ldg(&g_scratch[sb[4 + s] + l]);
    d = __ldg(&g_scratch[sb[8 + s] + l]);
}

__device__ __forceinline__ void stats(float a, float b, float d,
                                      float& mx, float& mn, float& sd) {
    mx = fmaxf(a, fmaxf(b, d));
    mn = (a + b + d) * (1.0f / 3.0f);
    float e0 = a - mn, e1 = b - mn, e2 = d - mn;
    sd = sqrtf((e0 * e0 + e1 * e1 + e2 * e2) * (1.0f / 3.0f));
}

__global__ __launch_bounds__(256, 8) void main_kernel(const float* __restrict__ inputs,
                                                      float* __restrict__ out) {
    __shared__ int sb[12];   // [v*4 + s]
    int row = blockIdx.x;
    int tid = threadIdx.x;
    size_t base = (size_t)row * OUT_COLS;

    if (tid < 3) {
        int v = tid;
        float in0 = inputs[row * 3 + 0];
        float in1 = inputs[row * 3 + 1];
        float in2 = inputs[row * 3 + 2];
        const float* C = g_consts;
        float po[3];
        #pragma unroll
        for (int k = 0; k < 3; k++)
            po[k] = fmaf(in0, C[0 * 3 + k],
                    fmaf(in1, C[1 * 3 + k],
                    fmaf(in2, C[2 * 3 + k], C[9 + k])));
        const float* cv = C + 12 + v * 12;
        float d0 = po[0] - cv[9];
        float d1 = po[1] - cv[10];
        float d2 = po[2] - cv[11];
        float X = fmaf(d0, cv[0], fmaf(d1, cv[1], d2 * cv[2]));
        float Y = fmaf(d0, cv[3], fmaf(d1, cv[4], d2 * cv[5]));
        float Z = fmaf(d0, cv[6], fmaf(d1, cv[7], d2 * cv[8]));
        float nz = -Z;
        float h = fmaf(248.0f, __fdiv_rn(-Y, nz), 112.0f);
        float w = fmaf(248.0f, __fdiv_rn(X, nz), 112.0f);
        if (isnan(h)) h = 0.0f;
        if (isnan(w)) w = 0.0f;
        h = fminf(fmaxf(h, 0.0f), 223.0f);
        w = fminf(fmaxf(w, 0.0f), 223.0f);
        int h0 = (int)(h * 0.25f),    w0 = (int)(w * 0.25f);
        int h1 = (int)(h * 0.125f),   w1 = (int)(w * 0.125f);
        int h2 = (int)(h * 0.0625f),  w2 = (int)(w * 0.0625f);
        int h3 = (int)(h * 0.03125f), w3 = (int)(w * 0.03125f);
        sb[v * 4 + 0] = (h0 * 56 + w0) * 64;
        sb[v * 4 + 1] = 200704 + (h1 * 28 + w1) * 128;
        sb[v * 4 + 2] = 301056 + (h2 * 14 + w2) * 256;
        sb[v * 4 + 3] = 351232 + (h3 * 7 + w3) * 512;
        __stcs(&out[base + v], (v == 0) ? in0 : (v == 1) ? in1 : in2);
    }
    __syncthreads();

    float* orow = out + base + 3;              // channel 0 of section 0
    int gamma = (int)((base + 3) & 1);         // 0 -> channel addr even at c=0
    int npairs = 480 - gamma;                  // pairs c0 = gamma + 2p

    // ---- iteration 0: p = tid (always < npairs since npairs >= 479) ----
    {
        int c0 = gamma + 2 * tid;
        float ax, bx, dx, ay, by, dy;
        if (tid >= 224) {
            // c0 >= 448 -> both channels statically in section 3
            int l = c0 - 448;
            int B0 = sb[3], B1 = sb[7], B2 = sb[11];
            ax = __ldg(&g_scratch[B0 + l]);
            bx = __ldg(&g_scratch[B1 + l]);
            dx = __ldg(&g_scratch[B2 + l]);
            ay = __ldg(&g_scratch[B0 + l + 1]);
            by = __ldg(&g_scratch[B1 + l + 1]);
            dy = __ldg(&g_scratch[B2 + l + 1]);
        } else {
            gather3s(c0,     sb, ax, bx, dx);
            gather3s(c0 + 1, sb, ay, by, dy);
        }
        float2 mx2, mn2, sd2;
        stats(ax, bx, dx, mx2.x, mn2.x, sd2.x);
        stats(ay, by, dy, mx2.y, mn2.y, sd2.y);
        __stcs((float2*)(orow + c0), mx2);
        __stcs((float2*)(orow + 960 + c0), mn2);
        __stcs((float2*)(orow + 1920 + c0), sd2);
    }

    // ---- iteration 1: p = tid + 256 -> c0 >= 512, statically section 3 ----
    {
        int p = tid + 256;
        if (p < npairs) {
            int c0 = gamma + 2 * p;
            int l = c0 - 448;
            int B0 = sb[3], B1 = sb[7], B2 = sb[11];
            float ax = __ldg(&g_scratch[B0 + l]);
            float bx = __ldg(&g_scratch[B1 + l]);
            float dx = __ldg(&g_scratch[B2 + l]);
            float ay = __ldg(&g_scratch[B0 + l + 1]);
            float by = __ldg(&g_scratch[B1 + l + 1]);
            float dy = __ldg(&g_scratch[B2 + l + 1]);
            float2 mx2, mn2, sd2;
            stats(ax, bx, dx, mx2.x, mn2.x, sd2.x);
            stats(ay, by, dy, mx2.y, mn2.y, sd2.y);
            __stcs((float2*)(orow + c0), mx2);
            __stcs((float2*)(orow + 960 + c0), mn2);
            __stcs((float2*)(orow + 1920 + c0), sd2);
        }
    }

    // gamma=1 edge channels 0 and 959 (scalar)
    if (gamma && tid < 2) {
        int c = tid ? 959 : 0;
        float a, b, d;
        gather3s(c, sb, a, b, d);
        float mx, mn, sd;
        stats(a, b, d, mx, mn, sd);
        __stcs(&orow[c], mx);
        __stcs(&orow[960 + c], mn);
        __stcs(&orow[1920 + c], sd);
    }
}

extern "C" void kernel_launch(void* const* d_in, const int* in_sizes, int n_in,
                              void* d_out, int out_size) {
    const float* inputs  = (const float*)d_in[0];
    const float* cameras = (const float*)d_in[1];
    const float* f0 = (const float*)d_in[2];
    const float* f1 = (const float*)d_in[3];
    const float* f2 = (const float*)d_in[4];
    const float* f3 = (const float*)d_in[5];
    float* out = (float*)d_out;

    int n = in_sizes[0] / 3;

    prep_kernel<<<(376320 + 255) / 256, 256>>>(f0, f1, f2, f3, cameras);
    main_kernel<<<n, 256>>>(inputs, out);
}

// round 13
// speedup vs baseline: 1.3722x; 1.0368x over previous
#include <cuda_runtime.h>
#include <math.h>

#define OUT_COLS 2883

// scratch: batch-0 features transposed to [H,W,C], concatenated per scale
//   s0: [56*56,64]  @ 0        s1: [28*28,128] @ 200704
//   s2: [14*14,256] @ 301056   s3: [7*7,512]   @ 351232
__device__ float g_scratch[376320];
// consts: [0..8] Minv[d][k], [9..11] o0; per view v at 12+v*12: c[v][k][d], o_v at +9..11
__device__ float g_consts[12 + 3 * 12];

// Fused: feature transpose (all blocks) + camera constants (block 0, threads 0-2)
__global__ void prep_kernel(const float* __restrict__ f0,
                            const float* __restrict__ f1,
                            const float* __restrict__ f2,
                            const float* __restrict__ f3,
                            const float* __restrict__ cameras) {
    if (blockIdx.x == 0 && threadIdx.x < 3) {
        const float PIF = 3.14159274101257324f;
        int v = threadIdx.x;
        float th = cameras[v * 5 + 0] * (PIF / 180.0f);
        float ph = cameras[v * 5 + 1] * (PIF / 180.0f);
        float r  = cameras[v * 5 + 3];
        float camy = r * sinf(ph);
        float lens = r * cosf(ph);
        float camx = lens * cosf(th);
        float camz = lens * sinf(th);
        float Z[3] = {camx, camy, camz};
        float Y[3] = {camy * cosf(th + PIF), lens, camy * sinf(th + PIF)};
        float X[3] = {Y[1] * Z[2] - Y[2] * Z[1],
                      Y[2] * Z[0] - Y[0] * Z[2],
                      Y[0] * Z[1] - Y[1] * Z[0]};
        float nx = sqrtf(X[0]*X[0] + X[1]*X[1] + X[2]*X[2]);
        float ny = sqrtf(Y[0]*Y[0] + Y[1]*Y[1] + Y[2]*Y[2]);
        float nz = sqrtf(Z[0]*Z[0] + Z[1]*Z[1] + Z[2]*Z[2]);
        float cn[3][3];
        for (int d = 0; d < 3; d++) {
            cn[0][d] = X[d] / nx;
            cn[1][d] = Y[d] / ny;
            cn[2][d] = Z[d] / nz;
        }
        for (int k = 0; k < 3; k++)
            for (int d = 0; d < 3; d++)
                g_consts[12 + v * 12 + k * 3 + d] = cn[k][d];
        for (int d = 0; d < 3; d++)
            g_consts[12 + v * 12 + 9 + d] = Z[d];

        if (v == 0) {
            double A[3][3];
            for (int i = 0; i < 3; i++)
                for (int j = 0; j < 3; j++)
                    A[i][j] = (double)cn[j][i];
            double det = A[0][0] * (A[1][1]*A[2][2] - A[1][2]*A[2][1])
                       + A[0][1] * (A[1][2]*A[2][0] - A[1][0]*A[2][2])
                       + A[0][2] * (A[1][0]*A[2][1] - A[1][1]*A[2][0]);
            double inv[3][3];
            inv[0][0] = (A[1][1]*A[2][2] - A[1][2]*A[2][1]) / det;
            inv[0][1] = (A[0][2]*A[2][1] - A[0][1]*A[2][2]) / det;
            inv[0][2] = (A[0][1]*A[1][2] - A[0][2]*A[1][1]) / det;
            inv[1][0] = (A[1][2]*A[2][0] - A[1][0]*A[2][2]) / det;
            inv[1][1] = (A[0][0]*A[2][2] - A[0][2]*A[2][0]) / det;
            inv[1][2] = (A[0][2]*A[1][0] - A[0][0]*A[1][2]) / det;
            inv[2][0] = (A[1][0]*A[2][1] - A[1][1]*A[2][0]) / det;
            inv[2][1] = (A[0][1]*A[2][0] - A[0][0]*A[2][1]) / det;
            inv[2][2] = (A[0][0]*A[1][1] - A[0][1]*A[1][0]) / det;
            for (int d = 0; d < 3; d++)
                for (int k = 0; k < 3; k++)
                    g_consts[d * 3 + k] = (float)inv[d][k];
            for (int d = 0; d < 3; d++)
                g_consts[9 + d] = Z[d];
        }
    }

    int i = blockIdx.x * blockDim.x + threadIdx.x;
    if (i >= 376320) return;
    float v;
    if (i < 200704)      { int c = i & 63;  int p = i >> 6;                 v = f0[c * 3136 + p]; }
    else if (i < 301056) { int l = i - 200704; int c = l & 127; int p = l >> 7; v = f1[c * 784 + p]; }
    else if (i < 351232) { int l = i - 301056; int c = l & 255; int p = l >> 8; v = f2[c * 196 + p]; }
    else                 { int l = i - 351232; int c = l & 511; int p = l >> 9; v = f3[c * 49 + p]; }
    g_scratch[i] = v;
}

// scalar gather of one channel's (a,b,d); bases from shared (broadcast LDS)
__device__ __forceinline__ void gather3s(int c, const int* sb,
                                         float& a, float& b, float& d) {
    int s, l;
    if (c < 64)       { s = 0; l = c; }
    else if (c < 192) { s = 1; l = c - 64; }
    else if (c < 448) { s = 2; l = c - 192; }
    else              { s = 3; l = c - 448; }
    a = __ldg(&g_scratch[sb[s] + l]);
    b = __ldg(&g_scratch[sb[4 + s] + l]);
    d = __ldg(&g_scratch[sb[8 + s] + l]);
}

__device__ __forceinline__ void stats(float a, float b, float d,
                                      float& mx, float& mn, float& sd) {
    mx = fmaxf(a, fmaxf(b, d));
    mn = (a + b + d) * (1.0f / 3.0f);
    float e0 = a - mn, e1 = b - mn, e2 = d - mn;
    sd = sqrtf((e0 * e0 + e1 * e1 + e2 * e2) * (1.0f / 3.0f));
}

// pair stats from three float2 gathers -> three float2 results, then store
__device__ __forceinline__ void stats2_store(float2 a2, float2 b2, float2 d2,
                                             float* orow, int c0) {
    float2 mx2, mn2, sd2;
    stats(a2.x, b2.x, d2.x, mx2.x, mn2.x, sd2.x);
    stats(a2.y, b2.y, d2.y, mx2.y, mn2.y, sd2.y);
    __stcs((float2*)(orow + c0), mx2);
    __stcs((float2*)(orow + 960 + c0), mn2);
    __stcs((float2*)(orow + 1920 + c0), sd2);
}

__global__ __launch_bounds__(256, 8) void main_kernel(const float* __restrict__ inputs,
                                                      float* __restrict__ out) {
    __shared__ int sb[12];   // [v*4 + s]
    int row = blockIdx.x;
    int tid = threadIdx.x;
    size_t base = (size_t)row * OUT_COLS;

    if (tid < 3) {
        int v = tid;
        float in0 = inputs[row * 3 + 0];
        float in1 = inputs[row * 3 + 1];
        float in2 = inputs[row * 3 + 2];
        const float* C = g_consts;
        float po[3];
        #pragma unroll
        for (int k = 0; k < 3; k++)
            po[k] = fmaf(in0, C[0 * 3 + k],
                    fmaf(in1, C[1 * 3 + k],
                    fmaf(in2, C[2 * 3 + k], C[9 + k])));
        const float* cv = C + 12 + v * 12;
        float d0 = po[0] - cv[9];
        float d1 = po[1] - cv[10];
        float d2 = po[2] - cv[11];
        float X = fmaf(d0, cv[0], fmaf(d1, cv[1], d2 * cv[2]));
        float Y = fmaf(d0, cv[3], fmaf(d1, cv[4], d2 * cv[5]));
        float Z = fmaf(d0, cv[6], fmaf(d1, cv[7], d2 * cv[8]));
        float nz = -Z;
        float h = fmaf(248.0f, __fdiv_rn(-Y, nz), 112.0f);
        float w = fmaf(248.0f, __fdiv_rn(X, nz), 112.0f);
        if (isnan(h)) h = 0.0f;
        if (isnan(w)) w = 0.0f;
        h = fminf(fmaxf(h, 0.0f), 223.0f);
        w = fminf(fmaxf(w, 0.0f), 223.0f);
        int h0 = (int)(h * 0.25f),    w0 = (int)(w * 0.25f);
        int h1 = (int)(h * 0.125f),   w1 = (int)(w * 0.125f);
        int h2 = (int)(h * 0.0625f),  w2 = (int)(w * 0.0625f);
        int h3 = (int)(h * 0.03125f), w3 = (int)(w * 0.03125f);
        sb[v * 4 + 0] = (h0 * 56 + w0) * 64;
        sb[v * 4 + 1] = 200704 + (h1 * 28 + w1) * 128;
        sb[v * 4 + 2] = 301056 + (h2 * 14 + w2) * 256;
        sb[v * 4 + 3] = 351232 + (h3 * 7 + w3) * 512;
        __stcs(&out[base + v], (v == 0) ? in0 : (v == 1) ? in1 : in2);
    }
    __syncthreads();

    float* orow = out + base + 3;              // channel 0 of section 0
    int gamma = (int)((base + 3) & 1);         // 0 -> channel addr even at c=0

    if (gamma == 0) {
        // ---- even rows: l = c0 - sect_start is even -> aligned float2 loads ----
        // iteration 0: c0 = 2*tid (0..510)
        {
            int c0 = 2 * tid;
            float2 a2, b2, d2;
            int s, l;
            if (c0 < 64)       { s = 0; l = c0; }
            else if (c0 < 192) { s = 1; l = c0 - 64; }
            else if (c0 < 448) { s = 2; l = c0 - 192; }
            else               { s = 3; l = c0 - 448; }
            a2 = __ldg((const float2*)&g_scratch[sb[s] + l]);
            b2 = __ldg((const float2*)&g_scratch[sb[4 + s] + l]);
            d2 = __ldg((const float2*)&g_scratch[sb[8 + s] + l]);
            stats2_store(a2, b2, d2, orow, c0);
        }
        // iteration 1: c0 = 512 + 2*tid, valid while c0 < 960 (tid < 224), static s3
        if (tid < 224) {
            int c0 = 512 + 2 * tid;
            int l = c0 - 448;
            float2 a2 = __ldg((const float2*)&g_scratch[sb[3] + l]);
            float2 b2 = __ldg((const float2*)&g_scratch[sb[7] + l]);
            float2 d2 = __ldg((const float2*)&g_scratch[sb[11] + l]);
            stats2_store(a2, b2, d2, orow, c0);
        }
    } else {
        // ---- odd rows: scalar loads (l odd), float2 stores ----
        // iteration 0: c0 = 1 + 2*tid
        {
            int c0 = 1 + 2 * tid;
            float ax, bx, dx, ay, by, dy;
            gather3s(c0,     sb, ax, bx, dx);
            gather3s(c0 + 1, sb, ay, by, dy);
            float2 a2 = {ax, ay}, b2 = {bx, by}, d2 = {dx, dy};
            stats2_store(a2, b2, d2, orow, c0);
        }
        // iteration 1: c0 = 513 + 2*tid, valid while c0+1 <= 958 (tid < 223), static s3
        if (tid < 223) {
            int c0 = 513 + 2 * tid;
            int l = c0 - 448;
            float ax = __ldg(&g_scratch[sb[3] + l]);
            float bx = __ldg(&g_scratch[sb[7] + l]);
            float dx = __ldg(&g_scratch[sb[11] + l]);
            float ay = __ldg(&g_scratch[sb[3] + l + 1]);
            float by = __ldg(&g_scratch[sb[7] + l + 1]);
            float dy = __ldg(&g_scratch[sb[11] + l + 1]);
            float2 a2 = {ax, ay}, b2 = {bx, by}, d2 = {dx, dy};
            stats2_store(a2, b2, d2, orow, c0);
        }
        // edge channels 0 and 959 (scalar)
        if (tid >= 224 && tid < 226) {
            int c = (tid == 224) ? 0 : 959;
            float a, b, d;
            gather3s(c, sb, a, b, d);
            float mx, mn, sd;
            stats(a, b, d, mx, mn, sd);
            __stcs(&orow[c], mx);
            __stcs(&orow[960 + c], mn);
            __stcs(&orow[1920 + c], sd);
        }
    }
}

extern "C" void kernel_launch(void* const* d_in, const int* in_sizes, int n_in,
                              void* d_out, int out_size) {
    const float* inputs  = (const float*)d_in[0];
    const float* cameras = (const float*)d_in[1];
    const float* f0 = (const float*)d_in[2];
    const float* f1 = (const float*)d_in[3];
    const float* f2 = (const float*)d_in[4];
    const float* f3 = (const float*)d_in[5];
    float* out = (float*)d_out;

    int n = in_sizes[0] / 3;

    prep_kernel<<<(376320 + 255) / 256, 256>>>(f0, f1, f2, f3, cameras);
    main_kernel<<<n, 256>>>(inputs, out);
}

// round 14
// speedup vs baseline: 1.4892x; 1.0853x over previous
#include <cuda_runtime.h>
#include <math.h>

#define OUT_COLS 2883

// scratch: batch-0 features transposed to [H,W,C], concatenated per scale
//   s0: [56*56,64]  @ 0        s1: [28*28,128] @ 200704
//   s2: [14*14,256] @ 301056   s3: [7*7,512]   @ 351232
__device__ float g_scratch[376320];
// consts: [0..8] Minv[d][k], [9..11] o0; per view v at 12+v*12: c[v][k][d], o_v at +9..11
__device__ float g_consts[12 + 3 * 12];

// Fused: feature transpose (all blocks) + camera constants (block 0, threads 0-2)
__global__ void prep_kernel(const float* __restrict__ f0,
                            const float* __restrict__ f1,
                            const float* __restrict__ f2,
                            const float* __restrict__ f3,
                            const float* __restrict__ cameras) {
    if (blockIdx.x == 0 && threadIdx.x < 3) {
        const float PIF = 3.14159274101257324f;
        int v = threadIdx.x;
        float th = cameras[v * 5 + 0] * (PIF / 180.0f);
        float ph = cameras[v * 5 + 1] * (PIF / 180.0f);
        float r  = cameras[v * 5 + 3];
        float camy = r * sinf(ph);
        float lens = r * cosf(ph);
        float camx = lens * cosf(th);
        float camz = lens * sinf(th);
        float Z[3] = {camx, camy, camz};
        float Y[3] = {camy * cosf(th + PIF), lens, camy * sinf(th + PIF)};
        float X[3] = {Y[1] * Z[2] - Y[2] * Z[1],
                      Y[2] * Z[0] - Y[0] * Z[2],
                      Y[0] * Z[1] - Y[1] * Z[0]};
        float nx = sqrtf(X[0]*X[0] + X[1]*X[1] + X[2]*X[2]);
        float ny = sqrtf(Y[0]*Y[0] + Y[1]*Y[1] + Y[2]*Y[2]);
        float nz = sqrtf(Z[0]*Z[0] + Z[1]*Z[1] + Z[2]*Z[2]);
        float cn[3][3];
        for (int d = 0; d < 3; d++) {
            cn[0][d] = X[d] / nx;
            cn[1][d] = Y[d] / ny;
            cn[2][d] = Z[d] / nz;
        }
        for (int k = 0; k < 3; k++)
            for (int d = 0; d < 3; d++)
                g_consts[12 + v * 12 + k * 3 + d] = cn[k][d];
        for (int d = 0; d < 3; d++)
            g_consts[12 + v * 12 + 9 + d] = Z[d];

        if (v == 0) {
            double A[3][3];
            for (int i = 0; i < 3; i++)
                for (int j = 0; j < 3; j++)
                    A[i][j] = (double)cn[j][i];
            double det = A[0][0] * (A[1][1]*A[2][2] - A[1][2]*A[2][1])
                       + A[0][1] * (A[1][2]*A[2][0] - A[1][0]*A[2][2])
                       + A[0][2] * (A[1][0]*A[2][1] - A[1][1]*A[2][0]);
            double inv[3][3];
            inv[0][0] = (A[1][1]*A[2][2] - A[1][2]*A[2][1]) / det;
            inv[0][1] = (A[0][2]*A[2][1] - A[0][1]*A[2][2]) / det;
            inv[0][2] = (A[0][1]*A[1][2] - A[0][2]*A[1][1]) / det;
            inv[1][0] = (A[1][2]*A[2][0] - A[1][0]*A[2][2]) / det;
            inv[1][1] = (A[0][0]*A[2][2] - A[0][2]*A[2][0]) / det;
            inv[1][2] = (A[0][2]*A[1][0] - A[0][0]*A[1][2]) / det;
            inv[2][0] = (A[1][0]*A[2][1] - A[1][1]*A[2][0]) / det;
            inv[2][1] = (A[0][1]*A[2][0] - A[0][0]*A[2][1]) / det;
            inv[2][2] = (A[0][0]*A[1][1] - A[0][1]*A[1][0]) / det;
            for (int d = 0; d < 3; d++)
                for (int k = 0; k < 3; k++)
                    g_consts[d * 3 + k] = (float)inv[d][k];
            for (int d = 0; d < 3; d++)
                g_consts[9 + d] = Z[d];
        }
    }

    int i = blockIdx.x * blockDim.x + threadIdx.x;
    if (i >= 376320) return;
    float v;
    if (i < 200704)      { int c = i & 63;  int p = i >> 6;                 v = f0[c * 3136 + p]; }
    else if (i < 301056) { int l = i - 200704; int c = l & 127; int p = l >> 7; v = f1[c * 784 + p]; }
    else if (i < 351232) { int l = i - 301056; int c = l & 255; int p = l >> 8; v = f2[c * 196 + p]; }
    else                 { int l = i - 351232; int c = l & 511; int p = l >> 9; v = f3[c * 49 + p]; }
    g_scratch[i] = v;
}

// scalar gather of one channel's (a,b,d); bases from shared (broadcast LDS)
__device__ __forceinline__ void gather3s(int c, const int* sb,
                                         float& a, float& b, float& d) {
    int s, l;
    if (c < 64)       { s = 0; l = c; }
    else if (c < 192) { s = 1; l = c - 64; }
    else if (c < 448) { s = 2; l = c - 192; }
    else              { s = 3; l = c - 448; }
    a = __ldg(&g_scratch[sb[s] + l]);
    b = __ldg(&g_scratch[sb[4 + s] + l]);
    d = __ldg(&g_scratch[sb[8 + s] + l]);
}

__device__ __forceinline__ void stats(float a, float b, float d,
                                      float& mx, float& mn, float& sd) {
    mx = fmaxf(a, fmaxf(b, d));
    mn = (a + b + d) * (1.0f / 3.0f);
    float e0 = a - mn, e1 = b - mn, e2 = d - mn;
    sd = sqrtf((e0 * e0 + e1 * e1 + e2 * e2) * (1.0f / 3.0f));
}

// pair stats from three float2 gathers -> three float2 results, then store
__device__ __forceinline__ void stats2_store(float2 a2, float2 b2, float2 d2,
                                             float* orow, int c0) {
    float2 mx2, mn2, sd2;
    stats(a2.x, b2.x, d2.x, mx2.x, mn2.x, sd2.x);
    stats(a2.y, b2.y, d2.y, mx2.y, mn2.y, sd2.y);
    __stcs((float2*)(orow + c0), mx2);
    __stcs((float2*)(orow + 960 + c0), mn2);
    __stcs((float2*)(orow + 1920 + c0), sd2);
}

// Two rows per block: rowE = 2*bid (gamma=1, scalar loads), rowO = 2*bid+1 (gamma=0, float2 loads)
__global__ __launch_bounds__(256, 8) void main_kernel(const float* __restrict__ inputs,
                                                      float* __restrict__ out) {
    __shared__ int sb[24];   // [r*12 + v*4 + s], r=0 even row, r=1 odd row
    int tid = threadIdx.x;
    int row0 = 2 * blockIdx.x;
    size_t base0 = (size_t)row0 * OUT_COLS;

    if (tid < 6) {
        int r = tid >= 3;           // 0: even row, 1: odd row
        int v = tid - 3 * r;
        int row = row0 + r;
        size_t base = base0 + (size_t)r * OUT_COLS;
        float in0 = inputs[row * 3 + 0];
        float in1 = inputs[row * 3 + 1];
        float in2 = inputs[row * 3 + 2];
        const float* C = g_consts;
        float po[3];
        #pragma unroll
        for (int k = 0; k < 3; k++)
            po[k] = fmaf(in0, C[0 * 3 + k],
                    fmaf(in1, C[1 * 3 + k],
                    fmaf(in2, C[2 * 3 + k], C[9 + k])));
        const float* cv = C + 12 + v * 12;
        float d0 = po[0] - cv[9];
        float d1 = po[1] - cv[10];
        float d2 = po[2] - cv[11];
        float X = fmaf(d0, cv[0], fmaf(d1, cv[1], d2 * cv[2]));
        float Y = fmaf(d0, cv[3], fmaf(d1, cv[4], d2 * cv[5]));
        float Z = fmaf(d0, cv[6], fmaf(d1, cv[7], d2 * cv[8]));
        float nz = -Z;
        float h = fmaf(248.0f, __fdiv_rn(-Y, nz), 112.0f);
        float w = fmaf(248.0f, __fdiv_rn(X, nz), 112.0f);
        if (isnan(h)) h = 0.0f;
        if (isnan(w)) w = 0.0f;
        h = fminf(fmaxf(h, 0.0f), 223.0f);
        w = fminf(fmaxf(w, 0.0f), 223.0f);
        int h0 = (int)(h * 0.25f),    w0 = (int)(w * 0.25f);
        int h1 = (int)(h * 0.125f),   w1 = (int)(w * 0.125f);
        int h2 = (int)(h * 0.0625f),  w2 = (int)(w * 0.0625f);
        int h3 = (int)(h * 0.03125f), w3 = (int)(w * 0.03125f);
        sb[r * 12 + v * 4 + 0] = (h0 * 56 + w0) * 64;
        sb[r * 12 + v * 4 + 1] = 200704 + (h1 * 28 + w1) * 128;
        sb[r * 12 + v * 4 + 2] = 301056 + (h2 * 14 + w2) * 256;
        sb[r * 12 + v * 4 + 3] = 351232 + (h3 * 7 + w3) * 512;
        __stcs(&out[base + v], (v == 0) ? in0 : (v == 1) ? in1 : in2);
    }
    __syncthreads();

    // ---------- odd row (r=1): base odd -> base+3 even -> gamma=0, float2 loads ----------
    {
        const int* sbr = sb + 12;
        float* orow = out + base0 + OUT_COLS + 3;
        // iteration 0: c0 = 2*tid (0..510)
        {
            int c0 = 2 * tid;
            int s, l;
            if (c0 < 64)       { s = 0; l = c0; }
            else if (c0 < 192) { s = 1; l = c0 - 64; }
            else if (c0 < 448) { s = 2; l = c0 - 192; }
            else               { s = 3; l = c0 - 448; }
            float2 a2 = __ldg((const float2*)&g_scratch[sbr[s] + l]);
            float2 b2 = __ldg((const float2*)&g_scratch[sbr[4 + s] + l]);
            float2 d2 = __ldg((const float2*)&g_scratch[sbr[8 + s] + l]);
            stats2_store(a2, b2, d2, orow, c0);
        }
        // iteration 1: c0 = 512 + 2*tid, tid < 224, static s3
        if (tid < 224) {
            int c0 = 512 + 2 * tid;
            int l = c0 - 448;
            float2 a2 = __ldg((const float2*)&g_scratch[sbr[3] + l]);
            float2 b2 = __ldg((const float2*)&g_scratch[sbr[7] + l]);
            float2 d2 = __ldg((const float2*)&g_scratch[sbr[11] + l]);
            stats2_store(a2, b2, d2, orow, c0);
        }
    }

    // ---------- even row (r=0): base even -> base+3 odd -> gamma=1, scalar loads ----------
    {
        const int* sbr = sb;
        float* orow = out + base0 + 3;
        // iteration 0: c0 = 1 + 2*tid
        {
            int c0 = 1 + 2 * tid;
            float ax, bx, dx, ay, by, dy;
            gather3s(c0,     sbr, ax, bx, dx);
            gather3s(c0 + 1, sbr, ay, by, dy);
            float2 a2 = {ax, ay}, b2 = {bx, by}, d2 = {dx, dy};
            stats2_store(a2, b2, d2, orow, c0);
        }
        // iteration 1: c0 = 513 + 2*tid, tid < 223, static s3
        if (tid < 223) {
            int c0 = 513 + 2 * tid;
            int l = c0 - 448;
            float ax = __ldg(&g_scratch[sbr[3] + l]);
            float bx = __ldg(&g_scratch[sbr[7] + l]);
            float dx = __ldg(&g_scratch[sbr[11] + l]);
            float ay = __ldg(&g_scratch[sbr[3] + l + 1]);
            float by = __ldg(&g_scratch[sbr[7] + l + 1]);
            float dy = __ldg(&g_scratch[sbr[11] + l + 1]);
            float2 a2 = {ax, ay}, b2 = {bx, by}, d2 = {dx, dy};
            stats2_store(a2, b2, d2, orow, c0);
        }
        // edge channels 0 and 959 (scalar)
        if (tid >= 224 && tid < 226) {
            int c = (tid == 224) ? 0 : 959;
            float a, b, d;
            gather3s(c, sbr, a, b, d);
            float mx, mn, sd;
            stats(a, b, d, mx, mn, sd);
            __stcs(&orow[c], mx);
            __stcs(&orow[960 + c], mn);
            __stcs(&orow[1920 + c], sd);
        }
    }
}

extern "C" void kernel_launch(void* const* d_in, const int* in_sizes, int n_in,
                              void* d_out, int out_size) {
    const float* inputs  = (const float*)d_in[0];
    const float* cameras = (const float*)d_in[1];
    const float* f0 = (const float*)d_in[2];
    const float* f1 = (const float*)d_in[3];
    const float* f2 = (const float*)d_in[4];
    const float* f3 = (const float*)d_in[5];
    float* out = (float*)d_out;

    int n = in_sizes[0] / 3;

    prep_kernel<<<(376320 + 255) / 256, 256>>>(f0, f1, f2, f3, cameras);
    main_kernel<<<n / 2, 256>>>(inputs, out);
}